// round 4
// baseline (speedup 1.0000x reference)
#include <cuda_runtime.h>
#include <math.h>

#define TT   2048
#define NBLK 128

// ---------------- static scratch (no allocations allowed) ----------------
__device__ float g_x0 [TT * 1088];        //  8.9 MB  embedded input
__device__ float g_xp0[TT * 8192];        // 64   MB  layer0 input projections (both dirs)
__device__ float g_h0 [TT * 2048];        // 16.8 MB  layer0 output [h_f | h_b]
__device__ float g_xp1[TT * 8192];        // 64   MB  layer1 input projections
__device__ float g_h1 [TT * 2048];        // 16.8 MB  layer1 output
__device__ float g_hstate[2][2048];       // double-buffered recurrent h [parity][dir*1024+j]
__device__ __align__(256) unsigned g_flag[2][64];  // per-dir, per-group monotone step flags

__global__ void reset_kernel() {
    if (threadIdx.x < 128) ((unsigned*)g_flag)[threadIdx.x] = 0u;
}

// ---------------- embedding concat ----------------
__global__ void embed_kernel(const float* __restrict__ sent,
                             const int*   __restrict__ tags,
                             const float* __restrict__ emb) {
    int t = blockIdx.x;
    float* dst = g_x0 + (size_t)t * 1088;
    const float* s = sent + (size_t)t * 1024;
    for (int i = threadIdx.x; i < 1024; i += blockDim.x) dst[i] = s[i];
    if (threadIdx.x < 64) {
        int tg = tags[t];
        dst[1024 + threadIdx.x] = emb[tg * 64 + threadIdx.x];
    }
}

// ---------------- tiled fp32 GEMM:  C[M,N] = A[M,K] @ B[N,K]^T + b1 + b2 ----------------
#define BM 128
#define BN 64
#define BK 16
#define ASTR (BM + 8)
#define BSTR (BN + 8)

__global__ __launch_bounds__(256) void gemm_bias_kernel(
    int N, int K,
    const float* __restrict__ A, int lda,
    const float* __restrict__ B, int ldb,
    const float* __restrict__ b1, const float* __restrict__ b2,
    float* __restrict__ C, int ldc)
{
    __shared__ float As[BK * ASTR];
    __shared__ float Bs[BK * BSTR];
    const int tid = threadIdx.x;
    const int tx = tid & 15, ty = tid >> 4;
    const int bm = blockIdx.y * BM, bn = blockIdx.x * BN;

    float acc[8][4];
#pragma unroll
    for (int m = 0; m < 8; m++)
#pragma unroll
        for (int n = 0; n < 4; n++) acc[m][n] = 0.f;

    const int brow = tid >> 2, bkq = tid & 3;

    for (int k0 = 0; k0 < K; k0 += BK) {
#pragma unroll
        for (int i = 0; i < 2; i++) {
            int f = tid + i * 256;
            int row = f >> 2, kq = f & 3;
            float4 v = *(const float4*)(A + (size_t)(bm + row) * lda + (k0 + kq * 4));
            As[(kq * 4 + 0) * ASTR + row] = v.x;
            As[(kq * 4 + 1) * ASTR + row] = v.y;
            As[(kq * 4 + 2) * ASTR + row] = v.z;
            As[(kq * 4 + 3) * ASTR + row] = v.w;
        }
        {
            float4 v = make_float4(0.f, 0.f, 0.f, 0.f);
            if (bn + brow < N)
                v = *(const float4*)(B + (size_t)(bn + brow) * ldb + (k0 + bkq * 4));
            Bs[(bkq * 4 + 0) * BSTR + brow] = v.x;
            Bs[(bkq * 4 + 1) * BSTR + brow] = v.y;
            Bs[(bkq * 4 + 2) * BSTR + brow] = v.z;
            Bs[(bkq * 4 + 3) * BSTR + brow] = v.w;
        }
        __syncthreads();
#pragma unroll
        for (int k = 0; k < BK; k++) {
            float4 a0 = *(const float4*)&As[k * ASTR + ty * 8];
            float4 a1 = *(const float4*)&As[k * ASTR + ty * 8 + 4];
            float4 bv = *(const float4*)&Bs[k * BSTR + tx * 4];
            float a[8] = {a0.x, a0.y, a0.z, a0.w, a1.x, a1.y, a1.z, a1.w};
            float bb[4] = {bv.x, bv.y, bv.z, bv.w};
#pragma unroll
            for (int m = 0; m < 8; m++)
#pragma unroll
                for (int n = 0; n < 4; n++)
                    acc[m][n] += a[m] * bb[n];
        }
        __syncthreads();
    }

#pragma unroll
    for (int n = 0; n < 4; n++) {
        int col = bn + tx * 4 + n;
        if (col >= N) continue;
        float bias = 0.f;
        if (b1) bias += b1[col];
        if (b2) bias += b2[col];
#pragma unroll
        for (int m = 0; m < 8; m++) {
            int row = bm + ty * 8 + m;
            C[(size_t)row * ldc + col] = acc[m][n] + bias;
        }
    }
}

// ---------------- persistent weight-stationary BiLSTM recurrence ----------------
// 128 blocks x 256 threads. Block b: dir = b>>6, owns h-indices grp*16 .. grp*16+15.
// Warp w owns 2 h-indices (jA=grp*16+2w, jB=jA+1) -> 8 gate rows.
// Rows i,f,g of jA in registers (96 f/thread); o(jA) + i,f,g,o(jB) in smem (40 rows).
// Inter-block sync: per-dir flag barrier (no atomics, no membar).

__device__ __forceinline__ float sigmoidf_(float x) { return 1.f / (1.f + expf(-x)); }

__device__ __forceinline__ void st_release_u32(unsigned* p, unsigned v) {
    asm volatile("st.release.gpu.global.u32 [%0], %1;" :: "l"(p), "r"(v) : "memory");
}
__device__ __forceinline__ unsigned long long ld_acquire_u64(const unsigned long long* p) {
    unsigned long long v;
    asm volatile("ld.acquire.gpu.global.u64 %0, [%1];" : "=l"(v) : "l"(p) : "memory");
    return v;
}

__global__ __launch_bounds__(256, 1) void rec_kernel(
    const float* __restrict__ xp,    // [T, 8192]  (dir*4096 + gate*1024 + j)
    const float* __restrict__ w_hh,  // [2, 4096, 1024]
    float* __restrict__ hout)        // [T, 2048]
{
    extern __shared__ float sm[];
    float* Ws  = sm;              // 40 rows x 1024
    float* h_s = sm + 40 * 1024;  // 1024

    const int tid  = threadIdx.x;
    const int w    = tid >> 5, lane = tid & 31;
    const int dir  = blockIdx.x >> 6;
    const int grp  = blockIdx.x & 63;
    const int jA   = grp * 16 + 2 * w;
    const int jB   = jA + 1;

    // load 40 smem-resident weight rows (warp ww, slot rr -> r = rr+3)
    for (int s = 0; s < 40; s++) {
        int ww = s / 5, rr = s % 5;
        int r = rr + 3;
        int j = grp * 16 + 2 * ww + ((r >= 4) ? 1 : 0);
        int gate = r & 3;
        const float4* src = (const float4*)(w_hh + ((size_t)dir * 4096 + gate * 1024 + j) * 1024);
        ((float4*)(Ws + s * 1024))[tid] = src[tid];
    }
    // 3 register-resident rows: gates i,f,g of jA; lane holds k = 4*lane + 128*q + u
    float wr[96];
#pragma unroll
    for (int r = 0; r < 3; r++) {
        const float4* src = (const float4*)(w_hh + ((size_t)dir * 4096 + r * 1024 + jA) * 1024);
#pragma unroll
        for (int q = 0; q < 8; q++) {
            float4 v = src[lane + q * 32];
            wr[r * 32 + q * 4 + 0] = v.x; wr[r * 32 + q * 4 + 1] = v.y;
            wr[r * 32 + q * 4 + 2] = v.z; wr[r * 32 + q * 4 + 3] = v.w;
        }
    }
    __syncthreads();

    float cA = 0.f, cB = 0.f;

    // prefetch xp for step 0
    const int t0 = (dir == 0) ? 0 : (TT - 1);
    const float* xr0 = xp + (size_t)t0 * 8192 + dir * 4096;
    float xiA = __ldg(xr0 + jA),        xfA = __ldg(xr0 + 1024 + jA);
    float xgA = __ldg(xr0 + 2048 + jA), xoA = __ldg(xr0 + 3072 + jA);
    float xiB = __ldg(xr0 + jB),        xfB = __ldg(xr0 + 1024 + jB);
    float xgB = __ldg(xr0 + 2048 + jB), xoB = __ldg(xr0 + 3072 + jB);

    for (int s = 0; s < TT; s++) {
        float h4x[32];
        if (s > 0) {
            // wait for all producers of this dir: flags[dir][*] >= s
            if (tid < 32) {
                const unsigned long long* fp =
                    (const unsigned long long*)&g_flag[dir][lane * 2];
                bool done = false;
                do {
                    unsigned long long v = ld_acquire_u64(fp);
                    done = ((unsigned)v >= (unsigned)s) &&
                           ((unsigned)(v >> 32) >= (unsigned)s);
                } while (!__all_sync(0xffffffffu, done));
            }
            __syncthreads();
            // stage h through smem; __ldcg -> L2 (skip possibly-stale L1)
            const float4* hp = (const float4*)(g_hstate[s & 1] + dir * 1024);
            float4 hv = __ldcg(hp + tid);
            ((float4*)h_s)[tid] = hv;
            __syncthreads();
#pragma unroll
            for (int q = 0; q < 8; q++) {
                float4 v = ((const float4*)h_s)[lane + q * 32];
                h4x[q * 4 + 0] = v.x; h4x[q * 4 + 1] = v.y;
                h4x[q * 4 + 2] = v.z; h4x[q * 4 + 3] = v.w;
            }
        } else {
#pragma unroll
            for (int i = 0; i < 32; i++) h4x[i] = 0.f;
        }

        float acc[8];
#pragma unroll
        for (int r = 0; r < 3; r++) {        // register rows
            float a = 0.f;
#pragma unroll
            for (int i = 0; i < 32; i++) a += wr[r * 32 + i] * h4x[i];
            acc[r] = a;
        }
#pragma unroll
        for (int rr = 0; rr < 5; rr++) {     // smem rows
            const float4* wsrow = (const float4*)(Ws + (w * 5 + rr) * 1024);
            float a = 0.f;
#pragma unroll
            for (int q = 0; q < 8; q++) {
                float4 v = wsrow[lane + q * 32];
                a += v.x * h4x[q * 4 + 0] + v.y * h4x[q * 4 + 1]
                   + v.z * h4x[q * 4 + 2] + v.w * h4x[q * 4 + 3];
            }
            acc[rr + 3] = a;
        }
#pragma unroll
        for (int r = 0; r < 8; r++) {
            float v = acc[r];
#pragma unroll
            for (int off = 16; off > 0; off >>= 1)
                v += __shfl_xor_sync(0xffffffffu, v, off);
            acc[r] = v;
        }

        const int t = (dir == 0) ? s : (TT - 1 - s);

        float iA = sigmoidf_(acc[0] + xiA);
        float fA = sigmoidf_(acc[1] + xfA);
        float gA = tanhf    (acc[2] + xgA);
        float oA = sigmoidf_(acc[3] + xoA);
        float iB = sigmoidf_(acc[4] + xiB);
        float fB = sigmoidf_(acc[5] + xfB);
        float gB = tanhf    (acc[6] + xgB);
        float oB = sigmoidf_(acc[7] + xoB);
        cA = fA * cA + iA * gA;
        cB = fB * cB + iB * gB;
        float hA = oA * tanhf(cA);
        float hB = oB * tanhf(cB);

        if (lane == 0) {
            float2 hv2 = make_float2(hA, hB);
            __stcg((float2*)(g_hstate[(s + 1) & 1] + dir * 1024 + jA), hv2);
            *(float2*)(hout + (size_t)t * 2048 + dir * 1024 + jA) = hv2;
        }

        // prefetch next step's xp (overlaps the flag publish + peer wait)
        if (s + 1 < TT) {
            const int tn = (dir == 0) ? (s + 1) : (TT - 2 - s);
            const float* xr = xp + (size_t)tn * 8192 + dir * 4096;
            xiA = __ldg(xr + jA);        xfA = __ldg(xr + 1024 + jA);
            xgA = __ldg(xr + 2048 + jA); xoA = __ldg(xr + 3072 + jA);
            xiB = __ldg(xr + jB);        xfB = __ldg(xr + 1024 + jB);
            xgB = __ldg(xr + 2048 + jB); xoB = __ldg(xr + 3072 + jB);
        }

        // publish: all h-stores of this block happen-before this release store
        __syncthreads();
        if (s + 1 < TT && tid == 0)
            st_release_u32(&g_flag[dir][grp], (unsigned)(s + 1));
    }
}

// ---------------- launch ----------------
extern "C" void kernel_launch(void* const* d_in, const int* in_sizes, int n_in,
                              void* d_out, int out_size) {
    const float* sentence = (const float*)d_in[0];
    const int*   tags     = (const int*)  d_in[1];
    const float* emb      = (const float*)d_in[2];
    const float* w_ih0    = (const float*)d_in[3];
    const float* w_hh0    = (const float*)d_in[4];
    const float* b_ih0    = (const float*)d_in[5];
    const float* b_hh0    = (const float*)d_in[6];
    const float* w_ih1    = (const float*)d_in[7];
    const float* w_hh1    = (const float*)d_in[8];
    const float* b_ih1    = (const float*)d_in[9];
    const float* b_hh1    = (const float*)d_in[10];
    const float* w_out    = (const float*)d_in[11];
    const float* b_out    = (const float*)d_in[12];
    float* out = (float*)d_out;

    const int REC_SMEM = 41 * 1024 * 4;  // 164 KB
    cudaFuncSetAttribute(rec_kernel, cudaFuncAttributeMaxDynamicSharedMemorySize, REC_SMEM);

    void *px0, *pxp0, *ph0, *pxp1, *ph1;
    cudaGetSymbolAddress(&px0,  g_x0);
    cudaGetSymbolAddress(&pxp0, g_xp0);
    cudaGetSymbolAddress(&ph0,  g_h0);
    cudaGetSymbolAddress(&pxp1, g_xp1);
    cudaGetSymbolAddress(&ph1,  g_h1);

    embed_kernel<<<TT, 256>>>(sentence, tags, emb);

    dim3 gproj(8192 / BN, TT / BM);
    gemm_bias_kernel<<<gproj, 256>>>(8192, 1088, (const float*)px0, 1088,
                                     w_ih0, 1088, b_ih0, b_hh0, (float*)pxp0, 8192);

    reset_kernel<<<1, 128>>>();
    rec_kernel<<<NBLK, 256, REC_SMEM>>>((const float*)pxp0, w_hh0, (float*)ph0);

    gemm_bias_kernel<<<gproj, 256>>>(8192, 2048, (const float*)ph0, 2048,
                                     w_ih1, 2048, b_ih1, b_hh1, (float*)pxp1, 8192);

    reset_kernel<<<1, 128>>>();
    rec_kernel<<<NBLK, 256, REC_SMEM>>>((const float*)pxp1, w_hh1, (float*)ph1);

    dim3 gout(1, TT / BM);
    gemm_bias_kernel<<<gout, 256>>>(50, 2048, (const float*)ph1, 2048,
                                    w_out, 2048, b_out, nullptr, out, 50);
}

// round 6
// speedup vs baseline: 1.9140x; 1.9140x over previous
#include <cuda_runtime.h>
#include <math.h>

#define TT   2048
#define NBLK 128

// ---------------- static scratch (no allocations allowed) ----------------
__device__ float g_x0 [TT * 1088];        //  8.9 MB  embedded input
__device__ float g_xp0[TT * 8192];        // 64   MB  layer0 input projections (both dirs)
__device__ float g_h0 [TT * 2048];        // 16.8 MB  layer0 output [h_f | h_b]
__device__ float g_xp1[TT * 8192];        // 64   MB  layer1 input projections
__device__ float g_h1 [TT * 2048];        // 16.8 MB  layer1 output
__device__ float g_hstate[2][2048];       // double-buffered recurrent h [parity][dir*1024+j]
__device__ __align__(256) unsigned g_cnt2[64];  // per-dir counters at [0] and [32] (128B apart)

__global__ void reset_kernel() {
    if (threadIdx.x < 64) g_cnt2[threadIdx.x] = 0u;
}

// ---------------- embedding concat ----------------
__global__ void embed_kernel(const float* __restrict__ sent,
                             const int*   __restrict__ tags,
                             const float* __restrict__ emb) {
    int t = blockIdx.x;
    float* dst = g_x0 + (size_t)t * 1088;
    const float* s = sent + (size_t)t * 1024;
    for (int i = threadIdx.x; i < 1024; i += blockDim.x) dst[i] = s[i];
    if (threadIdx.x < 64) {
        int tg = tags[t];
        dst[1024 + threadIdx.x] = emb[tg * 64 + threadIdx.x];
    }
}

// ---------------- f32x2 helpers ----------------
__device__ __forceinline__ unsigned long long fma2_(unsigned long long a,
                                                    unsigned long long b,
                                                    unsigned long long c) {
    unsigned long long d;
    asm("fma.rn.f32x2 %0, %1, %2, %3;" : "=l"(d) : "l"(a), "l"(b), "l"(c));
    return d;
}
__device__ __forceinline__ unsigned long long pack2_(float lo, float hi) {
    unsigned long long d;
    asm("mov.b64 %0, {%1, %2};" : "=l"(d) : "f"(lo), "f"(hi));
    return d;
}
__device__ __forceinline__ float2 unpack2_(unsigned long long v) {
    float lo, hi;
    asm("mov.b64 {%0, %1}, %2;" : "=f"(lo), "=f"(hi) : "l"(v));
    return make_float2(lo, hi);
}

// ---------------- tiled GEMM (packed f32x2 FMA):  C[M,N] = A[M,K] @ B[N,K]^T + b1 + b2 ----
#define BM 128
#define BN 64
#define BK 16
#define ASTR (BM + 8)
#define BSTR (BN + 8)

__global__ __launch_bounds__(256) void gemm_bias_kernel(
    int N, int K,
    const float* __restrict__ A, int lda,
    const float* __restrict__ B, int ldb,
    const float* __restrict__ b1, const float* __restrict__ b2,
    float* __restrict__ C, int ldc)
{
    __shared__ __align__(16) float As[BK * ASTR];
    __shared__ __align__(16) float Bs[BK * BSTR];
    const int tid = threadIdx.x;
    const int tx = tid & 15, ty = tid >> 4;
    const int bm = blockIdx.y * BM, bn = blockIdx.x * BN;

    unsigned long long acc2[4][4];   // m-pairs x n ; each holds rows (2mp, 2mp+1)
#pragma unroll
    for (int mp = 0; mp < 4; mp++)
#pragma unroll
        for (int n = 0; n < 4; n++) acc2[mp][n] = 0ull;

    const int brow = tid >> 2, bkq = tid & 3;

    for (int k0 = 0; k0 < K; k0 += BK) {
#pragma unroll
        for (int i = 0; i < 2; i++) {
            int f = tid + i * 256;
            int row = f >> 2, kq = f & 3;
            float4 v = *(const float4*)(A + (size_t)(bm + row) * lda + (k0 + kq * 4));
            As[(kq * 4 + 0) * ASTR + row] = v.x;
            As[(kq * 4 + 1) * ASTR + row] = v.y;
            As[(kq * 4 + 2) * ASTR + row] = v.z;
            As[(kq * 4 + 3) * ASTR + row] = v.w;
        }
        {
            float4 v = make_float4(0.f, 0.f, 0.f, 0.f);
            if (bn + brow < N)
                v = *(const float4*)(B + (size_t)(bn + brow) * ldb + (k0 + bkq * 4));
            Bs[(bkq * 4 + 0) * BSTR + brow] = v.x;
            Bs[(bkq * 4 + 1) * BSTR + brow] = v.y;
            Bs[(bkq * 4 + 2) * BSTR + brow] = v.z;
            Bs[(bkq * 4 + 3) * BSTR + brow] = v.w;
        }
        __syncthreads();
#pragma unroll
        for (int k = 0; k < BK; k++) {
            // A rows come out of smem already pair-packed (float4 = 2 x f32x2)
            ulonglong2 aA = *(const ulonglong2*)&As[k * ASTR + ty * 8];
            ulonglong2 aB = *(const ulonglong2*)&As[k * ASTR + ty * 8 + 4];
            float4 bv = *(const float4*)&Bs[k * BSTR + tx * 4];
            unsigned long long am[4] = {aA.x, aA.y, aB.x, aB.y};
            unsigned long long bd[4] = {pack2_(bv.x, bv.x), pack2_(bv.y, bv.y),
                                        pack2_(bv.z, bv.z), pack2_(bv.w, bv.w)};
#pragma unroll
            for (int mp = 0; mp < 4; mp++)
#pragma unroll
                for (int n = 0; n < 4; n++)
                    acc2[mp][n] = fma2_(am[mp], bd[n], acc2[mp][n]);
        }
        __syncthreads();
    }

#pragma unroll
    for (int n = 0; n < 4; n++) {
        int col = bn + tx * 4 + n;
        if (col >= N) continue;
        float bias = 0.f;
        if (b1) bias += b1[col];
        if (b2) bias += b2[col];
#pragma unroll
        for (int mp = 0; mp < 4; mp++) {
            float2 v = unpack2_(acc2[mp][n]);
            int row = bm + ty * 8 + 2 * mp;
            C[(size_t)row * ldc + col]       = v.x + bias;
            C[(size_t)(row + 1) * ldc + col] = v.y + bias;
        }
    }
}

// ---------------- persistent weight-stationary BiLSTM recurrence ----------------
// 128 blocks x 256 threads. Block b: dir = b>>6, owns h-indices grp*16 .. grp*16+15.
// Warp w owns 2 h-indices (jA=grp*16+2w, jB=jA+1) -> 8 gate rows.
// Rows i,f,g of jA in registers (96 f/thread); o(jA) + i,f,g,o(jB) in smem (40 rows).
// Inter-block sync: per-dir monotone counter, red.release publish + ld.acquire poll.

__device__ __forceinline__ float sigmoidf_(float x) { return 1.f / (1.f + expf(-x)); }

__device__ __forceinline__ void red_release_add(unsigned* p, unsigned v) {
    asm volatile("red.release.gpu.global.add.u32 [%0], %1;" :: "l"(p), "r"(v) : "memory");
}
__device__ __forceinline__ unsigned ld_acquire_u32(const unsigned* p) {
    unsigned v;
    asm volatile("ld.acquire.gpu.global.u32 %0, [%1];" : "=r"(v) : "l"(p) : "memory");
    return v;
}

__global__ __launch_bounds__(256, 1) void rec_kernel(
    const float* __restrict__ xp,    // [T, 8192]  (dir*4096 + gate*1024 + j)
    const float* __restrict__ w_hh,  // [2, 4096, 1024]
    float* __restrict__ hout)        // [T, 2048]
{
    extern __shared__ float sm[];
    float* Ws  = sm;              // 40 rows x 1024
    float* h_s = sm + 40 * 1024;  // 1024

    const int tid  = threadIdx.x;
    const int w    = tid >> 5, lane = tid & 31;
    const int dir  = blockIdx.x >> 6;
    const int grp  = blockIdx.x & 63;
    const int jA   = grp * 16 + 2 * w;
    const int jB   = jA + 1;
    unsigned* cnt  = &g_cnt2[dir * 32];

    // load 40 smem-resident weight rows (warp ww, slot rr -> r = rr+3)
    for (int s = 0; s < 40; s++) {
        int ww = s / 5, rr = s % 5;
        int r = rr + 3;
        int j = grp * 16 + 2 * ww + ((r >= 4) ? 1 : 0);
        int gate = r & 3;
        const float4* src = (const float4*)(w_hh + ((size_t)dir * 4096 + gate * 1024 + j) * 1024);
        ((float4*)(Ws + s * 1024))[tid] = src[tid];
    }
    // 3 register-resident rows: gates i,f,g of jA; lane holds k = 4*lane + 128*q + u
    float wr[96];
#pragma unroll
    for (int r = 0; r < 3; r++) {
        const float4* src = (const float4*)(w_hh + ((size_t)dir * 4096 + r * 1024 + jA) * 1024);
#pragma unroll
        for (int q = 0; q < 8; q++) {
            float4 v = src[lane + q * 32];
            wr[r * 32 + q * 4 + 0] = v.x; wr[r * 32 + q * 4 + 1] = v.y;
            wr[r * 32 + q * 4 + 2] = v.z; wr[r * 32 + q * 4 + 3] = v.w;
        }
    }
    __syncthreads();

    float cA = 0.f, cB = 0.f;

    // prefetch xp for step 0
    const int t0 = (dir == 0) ? 0 : (TT - 1);
    const float* xr0 = xp + (size_t)t0 * 8192 + dir * 4096;
    float xiA = __ldg(xr0 + jA),        xfA = __ldg(xr0 + 1024 + jA);
    float xgA = __ldg(xr0 + 2048 + jA), xoA = __ldg(xr0 + 3072 + jA);
    float xiB = __ldg(xr0 + jB),        xfB = __ldg(xr0 + 1024 + jB);
    float xgB = __ldg(xr0 + 2048 + jB), xoB = __ldg(xr0 + 3072 + jB);

    for (int s = 0; s < TT; s++) {
        float h4x[32];
        if (s > 0) {
            // wait for all 64 producers of this dir to have published step s
            if (tid == 0) {
                const unsigned target = (unsigned)s * 64u;
                while (ld_acquire_u32(cnt) < target) { }
            }
            __syncthreads();
            // stage h through smem; __ldcg -> L2 (skip possibly-stale L1)
            const float4* hp = (const float4*)(g_hstate[s & 1] + dir * 1024);
            float4 hv = __ldcg(hp + tid);
            ((float4*)h_s)[tid] = hv;
            __syncthreads();
#pragma unroll
            for (int q = 0; q < 8; q++) {
                float4 v = ((const float4*)h_s)[lane + q * 32];
                h4x[q * 4 + 0] = v.x; h4x[q * 4 + 1] = v.y;
                h4x[q * 4 + 2] = v.z; h4x[q * 4 + 3] = v.w;
            }
        } else {
#pragma unroll
            for (int i = 0; i < 32; i++) h4x[i] = 0.f;
        }

        float acc[8];
#pragma unroll
        for (int r = 0; r < 3; r++) {        // register rows
            float a = 0.f;
#pragma unroll
            for (int i = 0; i < 32; i++) a += wr[r * 32 + i] * h4x[i];
            acc[r] = a;
        }
#pragma unroll
        for (int rr = 0; rr < 5; rr++) {     // smem rows
            const float4* wsrow = (const float4*)(Ws + (w * 5 + rr) * 1024);
            float a = 0.f;
#pragma unroll
            for (int q = 0; q < 8; q++) {
                float4 v = wsrow[lane + q * 32];
                a += v.x * h4x[q * 4 + 0] + v.y * h4x[q * 4 + 1]
                   + v.z * h4x[q * 4 + 2] + v.w * h4x[q * 4 + 3];
            }
            acc[rr + 3] = a;
        }
#pragma unroll
        for (int r = 0; r < 8; r++) {
            float v = acc[r];
#pragma unroll
            for (int off = 16; off > 0; off >>= 1)
                v += __shfl_xor_sync(0xffffffffu, v, off);
            acc[r] = v;
        }

        float iA = sigmoidf_(acc[0] + xiA);
        float fA = sigmoidf_(acc[1] + xfA);
        float gA = tanhf    (acc[2] + xgA);
        float oA = sigmoidf_(acc[3] + xoA);
        float iB = sigmoidf_(acc[4] + xiB);
        float fB = sigmoidf_(acc[5] + xfB);
        float gB = tanhf    (acc[6] + xgB);
        float oB = sigmoidf_(acc[7] + xoB);
        cA = fA * cA + iA * gA;
        cB = fB * cB + iB * gB;
        float hA = oA * tanhf(cA);
        float hB = oB * tanhf(cB);

        float2 hv2 = make_float2(hA, hB);
        if (lane == 0)
            __stcg((float2*)(g_hstate[(s + 1) & 1] + dir * 1024 + jA), hv2);

        // publish FIRST (release orders the h-state stores via bar.sync + release)
        __syncthreads();
        if (tid == 0) red_release_add(cnt, 1u);

        // tail work overlaps peers' detect: hout store + next xp prefetch
        const int t = (dir == 0) ? s : (TT - 1 - s);
        if (lane == 0)
            *(float2*)(hout + (size_t)t * 2048 + dir * 1024 + jA) = hv2;

        if (s + 1 < TT) {
            const int tn = (dir == 0) ? (s + 1) : (TT - 2 - s);
            const float* xr = xp + (size_t)tn * 8192 + dir * 4096;
            xiA = __ldg(xr + jA);        xfA = __ldg(xr + 1024 + jA);
            xgA = __ldg(xr + 2048 + jA); xoA = __ldg(xr + 3072 + jA);
            xiB = __ldg(xr + jB);        xfB = __ldg(xr + 1024 + jB);
            xgB = __ldg(xr + 2048 + jB); xoB = __ldg(xr + 3072 + jB);
        }
    }
}

// ---------------- launch ----------------
extern "C" void kernel_launch(void* const* d_in, const int* in_sizes, int n_in,
                              void* d_out, int out_size) {
    const float* sentence = (const float*)d_in[0];
    const int*   tags     = (const int*)  d_in[1];
    const float* emb      = (const float*)d_in[2];
    const float* w_ih0    = (const float*)d_in[3];
    const float* w_hh0    = (const float*)d_in[4];
    const float* b_ih0    = (const float*)d_in[5];
    const float* b_hh0    = (const float*)d_in[6];
    const float* w_ih1    = (const float*)d_in[7];
    const float* w_hh1    = (const float*)d_in[8];
    const float* b_ih1    = (const float*)d_in[9];
    const float* b_hh1    = (const float*)d_in[10];
    const float* w_out    = (const float*)d_in[11];
    const float* b_out    = (const float*)d_in[12];
    float* out = (float*)d_out;

    const int REC_SMEM = 41 * 1024 * 4;  // 164 KB
    cudaFuncSetAttribute(rec_kernel, cudaFuncAttributeMaxDynamicSharedMemorySize, REC_SMEM);

    void *px0, *pxp0, *ph0, *pxp1, *ph1;
    cudaGetSymbolAddress(&px0,  g_x0);
    cudaGetSymbolAddress(&pxp0, g_xp0);
    cudaGetSymbolAddress(&ph0,  g_h0);
    cudaGetSymbolAddress(&pxp1, g_xp1);
    cudaGetSymbolAddress(&ph1,  g_h1);

    embed_kernel<<<TT, 256>>>(sentence, tags, emb);

    dim3 gproj(8192 / BN, TT / BM);
    gemm_bias_kernel<<<gproj, 256>>>(8192, 1088, (const float*)px0, 1088,
                                     w_ih0, 1088, b_ih0, b_hh0, (float*)pxp0, 8192);

    reset_kernel<<<1, 64>>>();
    rec_kernel<<<NBLK, 256, REC_SMEM>>>((const float*)pxp0, w_hh0, (float*)ph0);

    gemm_bias_kernel<<<gproj, 256>>>(8192, 2048, (const float*)ph0, 2048,
                                     w_ih1, 2048, b_ih1, b_hh1, (float*)pxp1, 8192);

    reset_kernel<<<1, 64>>>();
    rec_kernel<<<NBLK, 256, REC_SMEM>>>((const float*)pxp1, w_hh1, (float*)ph1);

    dim3 gout(1, TT / BM);
    gemm_bias_kernel<<<gout, 256>>>(50, 2048, (const float*)ph1, 2048,
                                    w_out, 2048, b_out, nullptr, out, 50);
}